// round 15
// baseline (speedup 1.0000x reference)
#include <cuda_runtime.h>
#include <cuda_fp16.h>
#include <cstdint>

#define B_    16
#define CIN   256
#define COUT  512
#define HB2   129   // blurred H/W

// Blurred intermediate NHWC-256 fp16; weights [tap][oc][cin] fp16.
static __device__ __align__(128) __half g_x[(size_t)B_ * HB2 * HB2 * CIN];
static __device__ __align__(128) __half g_w[9 * COUT * CIN];

// ---------------------------------------------------------------------------
__device__ __forceinline__ uint32_t smem_u32(const void* p) {
    uint32_t a;
    asm("{ .reg .u64 t; cvta.to.shared.u64 t, %1; cvt.u32.u64 %0, t; }" : "=r"(a) : "l"(p));
    return a;
}
__device__ __forceinline__ void cp16(uint32_t d, const void* s) {
    asm volatile("cp.async.cg.shared.global [%0], [%1], 16;" :: "r"(d), "l"(s));
}
__device__ __forceinline__ void cp_commit() {
    asm volatile("cp.async.commit_group;" ::: "memory");
}
__device__ __forceinline__ void cp_wait2() {
    asm volatile("cp.async.wait_group 2;" ::: "memory");
}
__device__ __forceinline__ void ldsm4(uint32_t* r, uint32_t a) {
    asm volatile("ldmatrix.sync.aligned.m8n8.x4.shared.b16 {%0,%1,%2,%3}, [%4];"
                 : "=r"(r[0]), "=r"(r[1]), "=r"(r[2]), "=r"(r[3]) : "r"(a));
}
__device__ __forceinline__ void ldsm4t(uint32_t* r, uint32_t a) {
    asm volatile("ldmatrix.sync.aligned.m8n8.x4.trans.shared.b16 {%0,%1,%2,%3}, [%4];"
                 : "=r"(r[0]), "=r"(r[1]), "=r"(r[2]), "=r"(r[3]) : "r"(a));
}
__device__ __forceinline__ void mma16816(float* c, const uint32_t* a, const uint32_t* b) {
    asm volatile(
        "mma.sync.aligned.m16n8k16.row.col.f32.f16.f16.f32 "
        "{%0,%1,%2,%3}, {%4,%5,%6,%7}, {%8,%9}, {%0,%1,%2,%3};"
        : "+f"(c[0]), "+f"(c[1]), "+f"(c[2]), "+f"(c[3])
        : "r"(a[0]), "r"(a[1]), "r"(a[2]), "r"(a[3]), "r"(b[0]), "r"(b[1]));
}

// ---------------------------------------------------------------------------
// Stage 1: separable 4x4 blur, NCHW fp32 -> NHWC-256 fp16. (R12 version)
// Processes 4 batches per launch (b = (blockIdx>>7)&3 + b_base).
// ---------------------------------------------------------------------------
__global__ void __launch_bounds__(256) blur_kernel(const float* __restrict__ x,
                                                   int b_base) {
    __shared__ __align__(16) __half st[8][8][136];   // 17408 B
    const int seg = blockIdx.x & 3;
    const int cb  = (blockIdx.x >> 2) & 31;          // 8-channel group
    const int b   = (blockIdx.x >> 7) + b_base;
    const int lane = threadIdx.x, c = threadIdx.y;
    const float* xc = x + ((size_t)(b * CIN + cb * 8 + c)) * (128 * 128);

    const int oh0 = seg * 33;
    const int ohN = (seg == 3) ? 30 : 33;            // 33+33+33+30 = 129

    float ring[4][4], ringE[4];
#pragma unroll
    for (int j = 0; j < 4; j++) {
        ringE[j] = 0.f;
#pragma unroll
        for (int k = 0; k < 4; k++) ring[j][k] = 0.f;
    }

    for (int it = 0; it < 9; it++) {
        float4 q4[4];
#pragma unroll
        for (int u = 0; u < 4; u++) {
            const int r = oh0 - 2 + 4 * it + u;
            q4[u] = make_float4(0.f, 0.f, 0.f, 0.f);
            if ((unsigned)r < 128u && r <= oh0 + ohN)
                q4[u] = *(const float4*)(xc + r * 128 + lane * 4);
        }
#pragma unroll
        for (int u = 0; u < 4; u++) {
            const int r = oh0 - 2 + 4 * it + u;
            if (r > oh0 + ohN) break;
            float4 q = q4[u];
            float pz = __shfl_up_sync(0xffffffffu, q.z, 1);
            float pw = __shfl_up_sync(0xffffffffu, q.w, 1);
            float nx = __shfl_down_sync(0xffffffffu, q.x, 1);
            if (lane == 0)  { pz = 0.f; pw = 0.f; }
            if (lane == 31) { nx = 0.f; }
            const int u0 = (u + 2) & 3;
            ring[u0][0] = 0.125f * (pz + q.y)  + 0.375f * (pw + q.x);
            ring[u0][1] = 0.125f * (pw + q.z)  + 0.375f * (q.x + q.y);
            ring[u0][2] = 0.125f * (q.x + q.w) + 0.375f * (q.y + q.z);
            ring[u0][3] = 0.125f * (q.y + nx)  + 0.375f * (q.z + q.w);
            ringE[u0]   = 0.125f * q.z + 0.375f * q.w;   // w=128 (lane 31)

            const int ohl = r - 1 - oh0;
            if (ohl >= 0 && ohl < ohN) {
                const int s0 = (u + 3) & 3, s1 = u & 3, s2 = (u + 1) & 3, s3 = u0;
                const int slot = ohl & 7;
                float o0 = 0.125f * (ring[s0][0] + ring[s3][0]) + 0.375f * (ring[s1][0] + ring[s2][0]);
                float o1 = 0.125f * (ring[s0][1] + ring[s3][1]) + 0.375f * (ring[s1][1] + ring[s2][1]);
                float o2 = 0.125f * (ring[s0][2] + ring[s3][2]) + 0.375f * (ring[s1][2] + ring[s2][2]);
                float o3 = 0.125f * (ring[s0][3] + ring[s3][3]) + 0.375f * (ring[s1][3] + ring[s2][3]);
                *(__half2*)&st[slot][c][4 * lane]     = __floats2half2_rn(o0, o1);
                *(__half2*)&st[slot][c][4 * lane + 2] = __floats2half2_rn(o2, o3);
                if (lane == 31) {
                    float oE = 0.125f * (ringE[s0] + ringE[s3])
                             + 0.375f * (ringE[s1] + ringE[s2]);
                    st[slot][c][128] = __float2half_rn(oE);
                }
                if ((ohl & 7) == 7 || ohl == ohN - 1) {
                    __syncthreads();
                    const int fbase = ohl & ~7;
                    const int wid = c;                   // warp = flush row
                    if (fbase + wid <= ohl) {
                        const int oh2 = oh0 + fbase + wid;
                        uint32_t* gw = (uint32_t*)(g_x
                            + ((size_t)(b * HB2 + oh2)) * HB2 * CIN) + cb * 4;
#pragma unroll
                        for (int t = 0; t < 4; t++) {
                            uint32_t rg[4];
                            uint32_t a = smem_u32(&st[wid][lane & 7][32 * t + 8 * (lane >> 3)]);
                            ldsm4t(rg, a);
#pragma unroll
                            for (int k = 0; k < 4; k++)
                                gw[(32 * t + 8 * k + (lane >> 2)) * 128 + (lane & 3)] = rg[k];
                        }
                        if (lane < 8)   // w = 128 edge
                            ((__half*)gw)[128 * 256 + lane] = st[wid][lane][128];
                    }
                    __syncthreads();
                }
            }
        }
    }
}

// ---------------------------------------------------------------------------
// Weight prep: w[3][3][CIN][COUT] fp32 -> g_w[tap][COUT][CIN] fp16, * 1/48.
// ---------------------------------------------------------------------------
__global__ void __launch_bounds__(256) wprep_kernel(const float* __restrict__ w) {
    __shared__ float t[32][33];
    const int tap = blockIdx.z, o0 = blockIdx.x * 32, cb0 = blockIdx.y * 32;
    const int tx = threadIdx.x, ty = threadIdx.y;
    const float sc = 1.0f / 48.0f;
    for (int r = ty; r < 32; r += 8)
        t[r][tx] = w[((size_t)tap * CIN + cb0 + r) * COUT + o0 + tx] * sc;
    __syncthreads();
    for (int r = ty; r < 32; r += 8)
        g_w[((size_t)tap * COUT + o0 + r) * CIN + cb0 + tx] = __float2half_rn(t[tx][r]);
}

// ---------------------------------------------------------------------------
// Stage 2: implicit GEMM via mma.sync (fp16 in, fp32 accum). KNOWN-GOOD R12.
// Processes 4 batches per launch (b = blockIdx.z + b_base).
// ---------------------------------------------------------------------------
#define TSTR  40                    // fp16 elements per smem row
#define STGB  20480                 // (128 A-rows + 128 B-rows) * 80B
#define SMEM_BYTES (4 * STGB)       // 81920

__global__ void __launch_bounds__(256, 2) conv_mma_kernel(
    const float* __restrict__ bias, float* __restrict__ out, int b_base)
{
    extern __shared__ char smem[];
    const uint32_t sA = smem_u32(smem);
    const int tid = threadIdx.x, lane = tid & 31, wid = tid >> 5;
    const int hb  = blockIdx.x * 2;     // 2 output rows per CTA
    const int oc0 = blockIdx.y * 128;
    const int b   = blockIdx.z + b_base;
    const int wm  = (wid & 3) * 32;     // warp m offset
    const int wn  = (wid >> 2) * 64;    // warp n offset

    float acc[2][8][4];
#pragma unroll
    for (int i = 0; i < 2; i++)
#pragma unroll
        for (int j = 0; j < 8; j++)
#pragma unroll
            for (int k = 0; k < 4; k++) acc[i][j][k] = 0.f;

    // Load mapping: thread -> row r (0..127), hk = which 16-cin half.
    const int r  = tid >> 1;
    const int hk = tid & 1;
    const int oh = hb + (r >> 6), ow = r & 63;

#define ISSUE_LOADS(chunk, stg)                                                  \
    {                                                                            \
        const int tap = (chunk) >> 3, c0 = ((chunk) & 7) << 5;                   \
        const int kh = tap / 3, kw = tap - kh * 3;                               \
        const size_t ao = (((size_t)(b * HB2 + 2 * oh + kh)) * HB2               \
                           + (2 * ow + kw)) * CIN + c0 + hk * 16;                \
        const size_t bo = ((size_t)(tap * COUT + oc0 + r)) * CIN + c0 + hk * 16; \
        const uint32_t d = sA + (stg) * STGB + r * 80 + hk * 32;                 \
        cp16(d, g_x + ao);              cp16(d + 16, g_x + ao + 8);              \
        const uint32_t e = d + 10240;                                            \
        cp16(e, g_w + bo);              cp16(e + 16, g_w + bo + 8);              \
    }

    ISSUE_LOADS(0, 0); cp_commit();
    ISSUE_LOADS(1, 1); cp_commit();
    ISSUE_LOADS(2, 2); cp_commit();

    for (int i = 0; i < 72; i++) {
        cp_wait2();
        __syncthreads();
        const uint32_t base = sA + (i & 3) * STGB;

#pragma unroll
        for (int ks = 0; ks < 32; ks += 16) {
            uint32_t af[2][4], bf[4][4];
#pragma unroll
            for (int mt = 0; mt < 2; mt++) {
                uint32_t a = base + ((wm + mt * 16 + (lane & 15)) * TSTR
                                     + ks + ((lane & 16) >> 1)) * 2;
                ldsm4(af[mt], a);
            }
#pragma unroll
            for (int bt = 0; bt < 4; bt++) {
                uint32_t a = base + 10240
                           + ((wn + bt * 16 + (lane & 7) + ((lane & 16) >> 1)) * TSTR
                              + ks + (lane & 8)) * 2;
                ldsm4(bf[bt], a);
            }
#pragma unroll
            for (int mt = 0; mt < 2; mt++)
#pragma unroll
                for (int bt = 0; bt < 4; bt++)
#pragma unroll
                    for (int h = 0; h < 2; h++)
                        mma16816(acc[mt][bt * 2 + h], af[mt], &bf[bt][2 * h]);
        }
        if (i + 3 < 72) ISSUE_LOADS(i + 3, (i + 3) & 3);
        cp_commit();
    }
    __syncthreads();   // all warps done reading stages before smem reuse

    // Epilogue: stage [oc_local][px] fp32 in smem, then coalesced writes.
    float* so = (float*)smem;           // 128 x 132 floats = 67.6KB <= 80KB
#pragma unroll
    for (int mt = 0; mt < 2; mt++)
#pragma unroll
        for (int nt = 0; nt < 8; nt++)
#pragma unroll
            for (int k = 0; k < 4; k++) {
                int px  = wm + mt * 16 + (lane >> 2) + ((k & 2) ? 8 : 0);
                int ocl = wn + nt * 8 + (lane & 3) * 2 + (k & 1);
                so[ocl * 132 + px] = acc[mt][nt][k];
            }
    __syncthreads();

    const int ocl = tid >> 1, pxb = (tid & 1) * 64;
    const float bv = bias[oc0 + ocl];
    const float gsc = 1.41421356237309515f;
    float* dst = out + (((size_t)(b * COUT + oc0 + ocl) * 64) + hb + (tid & 1)) * 64;
#pragma unroll
    for (int j = 0; j < 64; j += 4) {
        float4 v = *(const float4*)(so + ocl * 132 + pxb + j);
        v.x = ((v.x + bv) > 0.f ? (v.x + bv) : 0.2f * (v.x + bv)) * gsc;
        v.y = ((v.y + bv) > 0.f ? (v.y + bv) : 0.2f * (v.y + bv)) * gsc;
        v.z = ((v.z + bv) > 0.f ? (v.z + bv) : 0.2f * (v.z + bv)) * gsc;
        v.w = ((v.w + bv) > 0.f ? (v.w + bv) : 0.2f * (v.w + bv)) * gsc;
        *(float4*)(dst + j) = v;
    }
}

// ---------------------------------------------------------------------------
// Launch: 4 batch groups. Blur groups on the caller's stream; conv groups on
// a second stream gated per-group by events -> captured graph has parallel
// branches, so conv(g) overlaps blur(g+1..). Final event rejoins stream 0.
// Streams/events are created per call (capture+correctness only; replays do
// not re-enter) and intentionally not destroyed (host-side, bounded).
// ---------------------------------------------------------------------------
extern "C" void kernel_launch(void* const* d_in, const int* in_sizes, int n_in,
                              void* d_out, int out_size) {
    const float* x    = (const float*)d_in[0];   // [16,256,128,128]
    const float* w    = (const float*)d_in[1];   // [3,3,256,512]
    const float* bias = (const float*)d_in[2];   // [512]
    float* out = (float*)d_out;                  // [16,512,64,64]

    cudaFuncSetAttribute(conv_mma_kernel,
                         cudaFuncAttributeMaxDynamicSharedMemorySize, SMEM_BYTES);

    cudaStream_t s2;
    cudaStreamCreateWithFlags(&s2, cudaStreamNonBlocking);
    cudaEvent_t evB[4], evDone;
    for (int g = 0; g < 4; g++)
        cudaEventCreateWithFlags(&evB[g], cudaEventDisableTiming);
    cudaEventCreateWithFlags(&evDone, cudaEventDisableTiming);

    wprep_kernel<<<dim3(16, 8, 9), dim3(32, 8)>>>(w);
    for (int g = 0; g < 4; g++) {
        blur_kernel<<<512, dim3(32, 8)>>>(x, 4 * g);
        cudaEventRecord(evB[g], 0);
    }
    for (int g = 0; g < 4; g++) {
        cudaStreamWaitEvent(s2, evB[g], 0);
        conv_mma_kernel<<<dim3(32, 4, 4), 256, SMEM_BYTES, s2>>>(bias, out, 4 * g);
    }
    cudaEventRecord(evDone, s2);
    cudaStreamWaitEvent(0, evDone, 0);
}

// round 16
// speedup vs baseline: 1.0798x; 1.0798x over previous
#include <cuda_runtime.h>
#include <cuda_fp16.h>
#include <cstdint>

#define B_    16
#define CIN   256
#define COUT  512
#define HB2   129   // blurred H/W

// Blurred intermediate NHWC-256 fp16; weights [tap][oc][cin] fp16.
static __device__ __align__(128) __half g_x[(size_t)B_ * HB2 * HB2 * CIN];
static __device__ __align__(128) __half g_w[9 * COUT * CIN];

// ---------------------------------------------------------------------------
__device__ __forceinline__ uint32_t smem_u32(const void* p) {
    uint32_t a;
    asm("{ .reg .u64 t; cvta.to.shared.u64 t, %1; cvt.u32.u64 %0, t; }" : "=r"(a) : "l"(p));
    return a;
}
__device__ __forceinline__ void cp16(uint32_t d, const void* s) {
    asm volatile("cp.async.cg.shared.global [%0], [%1], 16;" :: "r"(d), "l"(s));
}
__device__ __forceinline__ void cp_commit() {
    asm volatile("cp.async.commit_group;" ::: "memory");
}
__device__ __forceinline__ void cp_wait2() {
    asm volatile("cp.async.wait_group 2;" ::: "memory");
}
__device__ __forceinline__ void ldsm4(uint32_t* r, uint32_t a) {
    asm volatile("ldmatrix.sync.aligned.m8n8.x4.shared.b16 {%0,%1,%2,%3}, [%4];"
                 : "=r"(r[0]), "=r"(r[1]), "=r"(r[2]), "=r"(r[3]) : "r"(a));
}
__device__ __forceinline__ void ldsm4t(uint32_t* r, uint32_t a) {
    asm volatile("ldmatrix.sync.aligned.m8n8.x4.trans.shared.b16 {%0,%1,%2,%3}, [%4];"
                 : "=r"(r[0]), "=r"(r[1]), "=r"(r[2]), "=r"(r[3]) : "r"(a));
}
__device__ __forceinline__ void mma16816(float* c, const uint32_t* a, const uint32_t* b) {
    asm volatile(
        "mma.sync.aligned.m16n8k16.row.col.f32.f16.f16.f32 "
        "{%0,%1,%2,%3}, {%4,%5,%6,%7}, {%8,%9}, {%0,%1,%2,%3};"
        : "+f"(c[0]), "+f"(c[1]), "+f"(c[2]), "+f"(c[3])
        : "r"(a[0]), "r"(a[1]), "r"(a[2]), "r"(a[3]), "r"(b[0]), "r"(b[1]));
}

// ---------------------------------------------------------------------------
// Stage 1: separable 4x4 blur, NCHW fp32 -> NHWC-256 fp16.
// CTA = 16-channel group; warp = 2 channels (c, c+8), MLP=8 batched loads,
// static register ring. Flush writes 32B pieces per pixel (FULL sectors).
// ---------------------------------------------------------------------------
__global__ void __launch_bounds__(256) blur_kernel(const float* __restrict__ x) {
    __shared__ __align__(16) __half st[8][16][136];   // 34816 B
    const int seg = blockIdx.x & 3;
    const int cb  = (blockIdx.x >> 2) & 15;          // 16-channel group
    const int b   = blockIdx.x >> 6;
    const int lane = threadIdx.x, c = threadIdx.y;   // c = 0..7
    const float* xc[2];
    xc[0] = x + ((size_t)(b * CIN + cb * 16 + c)) * (128 * 128);
    xc[1] = xc[0] + 8 * (128 * 128);

    const int oh0 = seg * 33;
    const int ohN = (seg == 3) ? 30 : 33;            // 33+33+33+30 = 129

    float ring[2][4][4], ringE[2][4];
#pragma unroll
    for (int cc = 0; cc < 2; cc++)
#pragma unroll
        for (int j = 0; j < 4; j++) {
            ringE[cc][j] = 0.f;
#pragma unroll
            for (int k = 0; k < 4; k++) ring[cc][j][k] = 0.f;
        }

    for (int it = 0; it < 9; it++) {
        // Batch 8 loads (2 channels x 4 rows): MLP = 8.
        float4 q4[2][4];
#pragma unroll
        for (int u = 0; u < 4; u++) {
            const int r = oh0 - 2 + 4 * it + u;
            const bool ok = ((unsigned)r < 128u) && (r <= oh0 + ohN);
#pragma unroll
            for (int cc = 0; cc < 2; cc++) {
                q4[cc][u] = make_float4(0.f, 0.f, 0.f, 0.f);
                if (ok) q4[cc][u] = *(const float4*)(xc[cc] + r * 128 + lane * 4);
            }
        }
#pragma unroll
        for (int u = 0; u < 4; u++) {
            const int r = oh0 - 2 + 4 * it + u;
            if (r > oh0 + ohN) break;
            const int u0 = (u + 2) & 3;                  // slot for row r
            const int s0 = (u + 3) & 3, s1 = u & 3, s2 = (u + 1) & 3, s3 = u0;
            const int ohl = r - 1 - oh0;
            const bool emit = (ohl >= 0 && ohl < ohN);
            const int slot = ohl & 7;
#pragma unroll
            for (int cc = 0; cc < 2; cc++) {
                float4 q = q4[cc][u];
                float pz = __shfl_up_sync(0xffffffffu, q.z, 1);
                float pw = __shfl_up_sync(0xffffffffu, q.w, 1);
                float nx = __shfl_down_sync(0xffffffffu, q.x, 1);
                if (lane == 0)  { pz = 0.f; pw = 0.f; }
                if (lane == 31) { nx = 0.f; }
                ring[cc][u0][0] = 0.125f * (pz + q.y)  + 0.375f * (pw + q.x);
                ring[cc][u0][1] = 0.125f * (pw + q.z)  + 0.375f * (q.x + q.y);
                ring[cc][u0][2] = 0.125f * (q.x + q.w) + 0.375f * (q.y + q.z);
                ring[cc][u0][3] = 0.125f * (q.y + nx)  + 0.375f * (q.z + q.w);
                ringE[cc][u0]   = 0.125f * q.z + 0.375f * q.w;   // w=128

                if (emit) {
                    const int ch = c + 8 * cc;
                    float o0 = 0.125f * (ring[cc][s0][0] + ring[cc][s3][0]) + 0.375f * (ring[cc][s1][0] + ring[cc][s2][0]);
                    float o1 = 0.125f * (ring[cc][s0][1] + ring[cc][s3][1]) + 0.375f * (ring[cc][s1][1] + ring[cc][s2][1]);
                    float o2 = 0.125f * (ring[cc][s0][2] + ring[cc][s3][2]) + 0.375f * (ring[cc][s1][2] + ring[cc][s2][2]);
                    float o3 = 0.125f * (ring[cc][s0][3] + ring[cc][s3][3]) + 0.375f * (ring[cc][s1][3] + ring[cc][s2][3]);
                    *(__half2*)&st[slot][ch][4 * lane]     = __floats2half2_rn(o0, o1);
                    *(__half2*)&st[slot][ch][4 * lane + 2] = __floats2half2_rn(o2, o3);
                    if (lane == 31) {
                        float oE = 0.125f * (ringE[cc][s0] + ringE[cc][s3])
                                 + 0.375f * (ringE[cc][s1] + ringE[cc][s2]);
                        st[slot][ch][128] = __float2half_rn(oE);
                    }
                }
            }
            if (emit && ((ohl & 7) == 7 || ohl == ohN - 1)) {
                __syncthreads();
                const int fbase = ohl & ~7;
                const int wid = c;                   // warp = flush row
                if (fbase + wid <= ohl) {
                    const int oh2 = oh0 + fbase + wid;
                    // 16 channels = 32B per pixel = 8 uint32 words, offset cb*8
                    uint32_t* gw = (uint32_t*)(g_x
                        + ((size_t)(b * HB2 + oh2)) * HB2 * CIN) + cb * 8;
#pragma unroll
                    for (int chh = 0; chh < 2; chh++)
#pragma unroll
                        for (int t = 0; t < 4; t++) {
                            uint32_t rg[4];
                            uint32_t a = smem_u32(
                                &st[wid][(lane & 7) + 8 * chh][32 * t + 8 * (lane >> 3)]);
                            ldsm4t(rg, a);
#pragma unroll
                            for (int k = 0; k < 4; k++)
                                gw[(32 * t + 8 * k + (lane >> 2)) * 128
                                   + chh * 4 + (lane & 3)] = rg[k];
                        }
                    if (lane < 16)   // w = 128 edge: 16 ch = 32B
                        ((__half*)gw)[128 * 256 + lane] = st[wid][lane][128];
                }
                __syncthreads();
            }
        }
    }
}

// ---------------------------------------------------------------------------
// Weight prep: w[3][3][CIN][COUT] fp32 -> g_w[tap][COUT][CIN] fp16, * 1/48.
// ---------------------------------------------------------------------------
__global__ void __launch_bounds__(256) wprep_kernel(const float* __restrict__ w) {
    __shared__ float t[32][33];
    const int tap = blockIdx.z, o0 = blockIdx.x * 32, cb0 = blockIdx.y * 32;
    const int tx = threadIdx.x, ty = threadIdx.y;
    const float sc = 1.0f / 48.0f;
    for (int r = ty; r < 32; r += 8)
        t[r][tx] = w[((size_t)tap * CIN + cb0 + r) * COUT + o0 + tx] * sc;
    __syncthreads();
    for (int r = ty; r < 32; r += 8)
        g_w[((size_t)tap * COUT + o0 + r) * CIN + cb0 + tx] = __float2half_rn(t[tx][r]);
}

// ---------------------------------------------------------------------------
// Stage 2: implicit GEMM via mma.sync (fp16 in, fp32 accum). KNOWN-GOOD R12.
// 256 thr = 8 warps (4m x 2n, warp 32x64), M=128 x N=128, K=2304 in 72
// chunks of 32, 4-stage ring, static (i&3), wait_group 2, 2 CTAs/SM.
// ---------------------------------------------------------------------------
#define TSTR  40                    // fp16 elements per smem row
#define STGB  20480                 // (128 A-rows + 128 B-rows) * 80B
#define SMEM_BYTES (4 * STGB)       // 81920

__global__ void __launch_bounds__(256, 2) conv_mma_kernel(
    const float* __restrict__ bias, float* __restrict__ out)
{
    extern __shared__ char smem[];
    const uint32_t sA = smem_u32(smem);
    const int tid = threadIdx.x, lane = tid & 31, wid = tid >> 5;
    const int hb  = blockIdx.x * 2;     // 2 output rows per CTA
    const int oc0 = blockIdx.y * 128;
    const int b   = blockIdx.z;
    const int wm  = (wid & 3) * 32;     // warp m offset
    const int wn  = (wid >> 2) * 64;    // warp n offset

    float acc[2][8][4];
#pragma unroll
    for (int i = 0; i < 2; i++)
#pragma unroll
        for (int j = 0; j < 8; j++)
#pragma unroll
            for (int k = 0; k < 4; k++) acc[i][j][k] = 0.f;

    // Load mapping: thread -> row r (0..127), hk = which 16-cin half.
    const int r  = tid >> 1;
    const int hk = tid & 1;
    const int oh = hb + (r >> 6), ow = r & 63;

#define ISSUE_LOADS(chunk, stg)                                                  \
    {                                                                            \
        const int tap = (chunk) >> 3, c0 = ((chunk) & 7) << 5;                   \
        const int kh = tap / 3, kw = tap - kh * 3;                               \
        const size_t ao = (((size_t)(b * HB2 + 2 * oh + kh)) * HB2               \
                           + (2 * ow + kw)) * CIN + c0 + hk * 16;                \
        const size_t bo = ((size_t)(tap * COUT + oc0 + r)) * CIN + c0 + hk * 16; \
        const uint32_t d = sA + (stg) * STGB + r * 80 + hk * 32;                 \
        cp16(d, g_x + ao);              cp16(d + 16, g_x + ao + 8);              \
        const uint32_t e = d + 10240;                                            \
        cp16(e, g_w + bo);              cp16(e + 16, g_w + bo + 8);              \
    }

    ISSUE_LOADS(0, 0); cp_commit();
    ISSUE_LOADS(1, 1); cp_commit();
    ISSUE_LOADS(2, 2); cp_commit();

    for (int i = 0; i < 72; i++) {
        cp_wait2();
        __syncthreads();
        const uint32_t base = sA + (i & 3) * STGB;

#pragma unroll
        for (int ks = 0; ks < 32; ks += 16) {
            uint32_t af[2][4], bf[4][4];
#pragma unroll
            for (int mt = 0; mt < 2; mt++) {
                uint32_t a = base + ((wm + mt * 16 + (lane & 15)) * TSTR
                                     + ks + ((lane & 16) >> 1)) * 2;
                ldsm4(af[mt], a);
            }
#pragma unroll
            for (int bt = 0; bt < 4; bt++) {
                uint32_t a = base + 10240
                           + ((wn + bt * 16 + (lane & 7) + ((lane & 16) >> 1)) * TSTR
                              + ks + (lane & 8)) * 2;
                ldsm4(bf[bt], a);
            }
#pragma unroll
            for (int mt = 0; mt < 2; mt++)
#pragma unroll
                for (int bt = 0; bt < 4; bt++)
#pragma unroll
                    for (int h = 0; h < 2; h++)
                        mma16816(acc[mt][bt * 2 + h], af[mt], &bf[bt][2 * h]);
        }
        if (i + 3 < 72) ISSUE_LOADS(i + 3, (i + 3) & 3);
        cp_commit();
    }
    __syncthreads();   // all warps done reading stages before smem reuse

    // Epilogue: stage [oc_local][px] fp32 in smem, then coalesced writes.
    float* so = (float*)smem;           // 128 x 132 floats = 67.6KB <= 80KB
#pragma unroll
    for (int mt = 0; mt < 2; mt++)
#pragma unroll
        for (int nt = 0; nt < 8; nt++)
#pragma unroll
            for (int k = 0; k < 4; k++) {
                int px  = wm + mt * 16 + (lane >> 2) + ((k & 2) ? 8 : 0);
                int ocl = wn + nt * 8 + (lane & 3) * 2 + (k & 1);
                so[ocl * 132 + px] = acc[mt][nt][k];
            }
    __syncthreads();

    const int ocl = tid >> 1, pxb = (tid & 1) * 64;
    const float bv = bias[oc0 + ocl];
    const float gsc = 1.41421356237309515f;
    float* dst = out + (((size_t)(b * COUT + oc0 + ocl) * 64) + hb + (tid & 1)) * 64;
#pragma unroll
    for (int j = 0; j < 64; j += 4) {
        float4 v = *(const float4*)(so + ocl * 132 + pxb + j);
        v.x = ((v.x + bv) > 0.f ? (v.x + bv) : 0.2f * (v.x + bv)) * gsc;
        v.y = ((v.y + bv) > 0.f ? (v.y + bv) : 0.2f * (v.y + bv)) * gsc;
        v.z = ((v.z + bv) > 0.f ? (v.z + bv) : 0.2f * (v.z + bv)) * gsc;
        v.w = ((v.w + bv) > 0.f ? (v.w + bv) : 0.2f * (v.w + bv)) * gsc;
        *(float4*)(dst + j) = v;
    }
}

// ---------------------------------------------------------------------------
extern "C" void kernel_launch(void* const* d_in, const int* in_sizes, int n_in,
                              void* d_out, int out_size) {
    const float* x    = (const float*)d_in[0];   // [16,256,128,128]
    const float* w    = (const float*)d_in[1];   // [3,3,256,512]
    const float* bias = (const float*)d_in[2];   // [512]
    float* out = (float*)d_out;                  // [16,512,64,64]

    cudaFuncSetAttribute(conv_mma_kernel,
                         cudaFuncAttributeMaxDynamicSharedMemorySize, SMEM_BYTES);

    blur_kernel<<<1024, dim3(32, 8)>>>(x);
    wprep_kernel<<<dim3(16, 8, 9), dim3(32, 8)>>>(w);
    conv_mma_kernel<<<dim3(32, 4, B_), 256, SMEM_BYTES>>>(bias, out);
}

// round 17
// speedup vs baseline: 1.0861x; 1.0059x over previous
#include <cuda_runtime.h>
#include <cuda_fp16.h>
#include <cstdint>

#define B_    16
#define CIN   256
#define COUT  512
#define HB2   129   // blurred H/W

// Blurred intermediate NHWC-256 fp16; weights [tap][oc][cin] fp16.
static __device__ __align__(128) __half g_x[(size_t)B_ * HB2 * HB2 * CIN];
static __device__ __align__(128) __half g_w[9 * COUT * CIN];

// ---------------------------------------------------------------------------
__device__ __forceinline__ uint32_t smem_u32(const void* p) {
    uint32_t a;
    asm("{ .reg .u64 t; cvta.to.shared.u64 t, %1; cvt.u32.u64 %0, t; }" : "=r"(a) : "l"(p));
    return a;
}
__device__ __forceinline__ void cp16(uint32_t d, const void* s) {
    asm volatile("cp.async.cg.shared.global [%0], [%1], 16;" :: "r"(d), "l"(s));
}
__device__ __forceinline__ void cp_commit() {
    asm volatile("cp.async.commit_group;" ::: "memory");
}
__device__ __forceinline__ void cp_wait2() {
    asm volatile("cp.async.wait_group 2;" ::: "memory");
}
__device__ __forceinline__ void ldsm4(uint32_t* r, uint32_t a) {
    asm volatile("ldmatrix.sync.aligned.m8n8.x4.shared.b16 {%0,%1,%2,%3}, [%4];"
                 : "=r"(r[0]), "=r"(r[1]), "=r"(r[2]), "=r"(r[3]) : "r"(a));
}
__device__ __forceinline__ void ldsm4t(uint32_t* r, uint32_t a) {
    asm volatile("ldmatrix.sync.aligned.m8n8.x4.trans.shared.b16 {%0,%1,%2,%3}, [%4];"
                 : "=r"(r[0]), "=r"(r[1]), "=r"(r[2]), "=r"(r[3]) : "r"(a));
}
__device__ __forceinline__ void mma16816(float* c, const uint32_t* a, const uint32_t* b) {
    asm volatile(
        "mma.sync.aligned.m16n8k16.row.col.f32.f16.f16.f32 "
        "{%0,%1,%2,%3}, {%4,%5,%6,%7}, {%8,%9}, {%0,%1,%2,%3};"
        : "+f"(c[0]), "+f"(c[1]), "+f"(c[2]), "+f"(c[3])
        : "r"(a[0]), "r"(a[1]), "r"(a[2]), "r"(a[3]), "r"(b[0]), "r"(b[1]));
}

// ---------------------------------------------------------------------------
// Stage 1: separable 4x4 blur, NCHW fp32 -> NHWC-256 fp16. (R12 body)
// Warp = one channel over a row segment (4/image), MLP=4 batched loads,
// static register ring, ldsm4t flush. NEW: minBlocks=4 -> 64-reg cap ->
// 4 CTAs/SM (32 warps) for the latency-bound main loop.
// ---------------------------------------------------------------------------
__global__ void __launch_bounds__(256, 4) blur_kernel(const float* __restrict__ x) {
    __shared__ __align__(16) __half st[8][8][136];   // 17408 B
    const int seg = blockIdx.x & 3;
    const int cb  = (blockIdx.x >> 2) & 31;          // 8-channel group
    const int b   = blockIdx.x >> 7;
    const int lane = threadIdx.x, c = threadIdx.y;
    const float* xc = x + ((size_t)(b * CIN + cb * 8 + c)) * (128 * 128);

    const int oh0 = seg * 33;
    const int ohN = (seg == 3) ? 30 : 33;            // 33+33+33+30 = 129

    float ring[4][4], ringE[4];
#pragma unroll
    for (int j = 0; j < 4; j++) {
        ringE[j] = 0.f;
#pragma unroll
        for (int k = 0; k < 4; k++) ring[j][k] = 0.f;
    }

    for (int it = 0; it < 9; it++) {
        float4 q4[4];
#pragma unroll
        for (int u = 0; u < 4; u++) {
            const int r = oh0 - 2 + 4 * it + u;
            q4[u] = make_float4(0.f, 0.f, 0.f, 0.f);
            if ((unsigned)r < 128u && r <= oh0 + ohN)
                q4[u] = *(const float4*)(xc + r * 128 + lane * 4);
        }
#pragma unroll
        for (int u = 0; u < 4; u++) {
            const int r = oh0 - 2 + 4 * it + u;
            if (r > oh0 + ohN) break;
            float4 q = q4[u];
            float pz = __shfl_up_sync(0xffffffffu, q.z, 1);
            float pw = __shfl_up_sync(0xffffffffu, q.w, 1);
            float nx = __shfl_down_sync(0xffffffffu, q.x, 1);
            if (lane == 0)  { pz = 0.f; pw = 0.f; }
            if (lane == 31) { nx = 0.f; }
            const int u0 = (u + 2) & 3;
            ring[u0][0] = 0.125f * (pz + q.y)  + 0.375f * (pw + q.x);
            ring[u0][1] = 0.125f * (pw + q.z)  + 0.375f * (q.x + q.y);
            ring[u0][2] = 0.125f * (q.x + q.w) + 0.375f * (q.y + q.z);
            ring[u0][3] = 0.125f * (q.y + nx)  + 0.375f * (q.z + q.w);
            ringE[u0]   = 0.125f * q.z + 0.375f * q.w;   // w=128 (lane 31)

            const int ohl = r - 1 - oh0;
            if (ohl >= 0 && ohl < ohN) {
                const int s0 = (u + 3) & 3, s1 = u & 3, s2 = (u + 1) & 3, s3 = u0;
                const int slot = ohl & 7;
                float o0 = 0.125f * (ring[s0][0] + ring[s3][0]) + 0.375f * (ring[s1][0] + ring[s2][0]);
                float o1 = 0.125f * (ring[s0][1] + ring[s3][1]) + 0.375f * (ring[s1][1] + ring[s2][1]);
                float o2 = 0.125f * (ring[s0][2] + ring[s3][2]) + 0.375f * (ring[s1][2] + ring[s2][2]);
                float o3 = 0.125f * (ring[s0][3] + ring[s3][3]) + 0.375f * (ring[s1][3] + ring[s2][3]);
                *(__half2*)&st[slot][c][4 * lane]     = __floats2half2_rn(o0, o1);
                *(__half2*)&st[slot][c][4 * lane + 2] = __floats2half2_rn(o2, o3);
                if (lane == 31) {
                    float oE = 0.125f * (ringE[s0] + ringE[s3])
                             + 0.375f * (ringE[s1] + ringE[s2]);
                    st[slot][c][128] = __float2half_rn(oE);
                }
                if ((ohl & 7) == 7 || ohl == ohN - 1) {
                    __syncthreads();
                    const int fbase = ohl & ~7;
                    const int wid = c;                   // warp = flush row
                    if (fbase + wid <= ohl) {
                        const int oh2 = oh0 + fbase + wid;
                        uint32_t* gw = (uint32_t*)(g_x
                            + ((size_t)(b * HB2 + oh2)) * HB2 * CIN) + cb * 4;
#pragma unroll
                        for (int t = 0; t < 4; t++) {
                            uint32_t rg[4];
                            uint32_t a = smem_u32(&st[wid][lane & 7][32 * t + 8 * (lane >> 3)]);
                            ldsm4t(rg, a);
#pragma unroll
                            for (int k = 0; k < 4; k++)
                                gw[(32 * t + 8 * k + (lane >> 2)) * 128 + (lane & 3)] = rg[k];
                        }
                        if (lane < 8)   // w = 128 edge
                            ((__half*)gw)[128 * 256 + lane] = st[wid][lane][128];
                    }
                    __syncthreads();
                }
            }
        }
    }
}

// ---------------------------------------------------------------------------
// Weight prep: w[3][3][CIN][COUT] fp32 -> g_w[tap][COUT][CIN] fp16, * 1/48.
// ---------------------------------------------------------------------------
__global__ void __launch_bounds__(256) wprep_kernel(const float* __restrict__ w) {
    __shared__ float t[32][33];
    const int tap = blockIdx.z, o0 = blockIdx.x * 32, cb0 = blockIdx.y * 32;
    const int tx = threadIdx.x, ty = threadIdx.y;
    const float sc = 1.0f / 48.0f;
    for (int r = ty; r < 32; r += 8)
        t[r][tx] = w[((size_t)tap * CIN + cb0 + r) * COUT + o0 + tx] * sc;
    __syncthreads();
    for (int r = ty; r < 32; r += 8)
        g_w[((size_t)tap * COUT + o0 + r) * CIN + cb0 + tx] = __float2half_rn(t[tx][r]);
}

// ---------------------------------------------------------------------------
// Stage 2: implicit GEMM via mma.sync (fp16 in, fp32 accum). KNOWN-GOOD R12.
// 256 thr = 8 warps (4m x 2n, warp 32x64), M=128 x N=128, K=2304 in 72
// chunks of 32, 4-stage ring, static (i&3), wait_group 2, 2 CTAs/SM.
// ---------------------------------------------------------------------------
#define TSTR  40                    // fp16 elements per smem row
#define STGB  20480                 // (128 A-rows + 128 B-rows) * 80B
#define SMEM_BYTES (4 * STGB)       // 81920

__global__ void __launch_bounds__(256, 2) conv_mma_kernel(
    const float* __restrict__ bias, float* __restrict__ out)
{
    extern __shared__ char smem[];
    const uint32_t sA = smem_u32(smem);
    const int tid = threadIdx.x, lane = tid & 31, wid = tid >> 5;
    const int hb  = blockIdx.x * 2;     // 2 output rows per CTA
    const int oc0 = blockIdx.y * 128;
    const int b   = blockIdx.z;
    const int wm  = (wid & 3) * 32;     // warp m offset
    const int wn  = (wid >> 2) * 64;    // warp n offset

    float acc[2][8][4];
#pragma unroll
    for (int i = 0; i < 2; i++)
#pragma unroll
        for (int j = 0; j < 8; j++)
#pragma unroll
            for (int k = 0; k < 4; k++) acc[i][j][k] = 0.f;

    // Load mapping: thread -> row r (0..127), hk = which 16-cin half.
    const int r  = tid >> 1;
    const int hk = tid & 1;
    const int oh = hb + (r >> 6), ow = r & 63;

#define ISSUE_LOADS(chunk, stg)                                                  \
    {                                                                            \
        const int tap = (chunk) >> 3, c0 = ((chunk) & 7) << 5;                   \
        const int kh = tap / 3, kw = tap - kh * 3;                               \
        const size_t ao = (((size_t)(b * HB2 + 2 * oh + kh)) * HB2               \
                           + (2 * ow + kw)) * CIN + c0 + hk * 16;                \
        const size_t bo = ((size_t)(tap * COUT + oc0 + r)) * CIN + c0 + hk * 16; \
        const uint32_t d = sA + (stg) * STGB + r * 80 + hk * 32;                 \
        cp16(d, g_x + ao);              cp16(d + 16, g_x + ao + 8);              \
        const uint32_t e = d + 10240;                                            \
        cp16(e, g_w + bo);              cp16(e + 16, g_w + bo + 8);              \
    }

    ISSUE_LOADS(0, 0); cp_commit();
    ISSUE_LOADS(1, 1); cp_commit();
    ISSUE_LOADS(2, 2); cp_commit();

    for (int i = 0; i < 72; i++) {
        cp_wait2();
        __syncthreads();
        const uint32_t base = sA + (i & 3) * STGB;

#pragma unroll
        for (int ks = 0; ks < 32; ks += 16) {
            uint32_t af[2][4], bf[4][4];
#pragma unroll
            for (int mt = 0; mt < 2; mt++) {
                uint32_t a = base + ((wm + mt * 16 + (lane & 15)) * TSTR
                                     + ks + ((lane & 16) >> 1)) * 2;
                ldsm4(af[mt], a);
            }
#pragma unroll
            for (int bt = 0; bt < 4; bt++) {
                uint32_t a = base + 10240
                           + ((wn + bt * 16 + (lane & 7) + ((lane & 16) >> 1)) * TSTR
                              + ks + (lane & 8)) * 2;
                ldsm4(bf[bt], a);
            }
#pragma unroll
            for (int mt = 0; mt < 2; mt++)
#pragma unroll
                for (int bt = 0; bt < 4; bt++)
#pragma unroll
                    for (int h = 0; h < 2; h++)
                        mma16816(acc[mt][bt * 2 + h], af[mt], &bf[bt][2 * h]);
        }
        if (i + 3 < 72) ISSUE_LOADS(i + 3, (i + 3) & 3);
        cp_commit();
    }
    __syncthreads();   // all warps done reading stages before smem reuse

    // Epilogue: stage [oc_local][px] fp32 in smem, then coalesced writes.
    float* so = (float*)smem;           // 128 x 132 floats = 67.6KB <= 80KB
#pragma unroll
    for (int mt = 0; mt < 2; mt++)
#pragma unroll
        for (int nt = 0; nt < 8; nt++)
#pragma unroll
            for (int k = 0; k < 4; k++) {
                int px  = wm + mt * 16 + (lane >> 2) + ((k & 2) ? 8 : 0);
                int ocl = wn + nt * 8 + (lane & 3) * 2 + (k & 1);
                so[ocl * 132 + px] = acc[mt][nt][k];
            }
    __syncthreads();

    const int ocl = tid >> 1, pxb = (tid & 1) * 64;
    const float bv = bias[oc0 + ocl];
    const float gsc = 1.41421356237309515f;
    float* dst = out + (((size_t)(b * COUT + oc0 + ocl) * 64) + hb + (tid & 1)) * 64;
#pragma unroll
    for (int j = 0; j < 64; j += 4) {
        float4 v = *(const float4*)(so + ocl * 132 + pxb + j);
        v.x = ((v.x + bv) > 0.f ? (v.x + bv) : 0.2f * (v.x + bv)) * gsc;
        v.y = ((v.y + bv) > 0.f ? (v.y + bv) : 0.2f * (v.y + bv)) * gsc;
        v.z = ((v.z + bv) > 0.f ? (v.z + bv) : 0.2f * (v.z + bv)) * gsc;
        v.w = ((v.w + bv) > 0.f ? (v.w + bv) : 0.2f * (v.w + bv)) * gsc;
        *(float4*)(dst + j) = v;
    }
}

// ---------------------------------------------------------------------------
extern "C" void kernel_launch(void* const* d_in, const int* in_sizes, int n_in,
                              void* d_out, int out_size) {
    const float* x    = (const float*)d_in[0];   // [16,256,128,128]
    const float* w    = (const float*)d_in[1];   // [3,3,256,512]
    const float* bias = (const float*)d_in[2];   // [512]
    float* out = (float*)d_out;                  // [16,512,64,64]

    cudaFuncSetAttribute(conv_mma_kernel,
                         cudaFuncAttributeMaxDynamicSharedMemorySize, SMEM_BYTES);

    blur_kernel<<<2048, dim3(32, 8)>>>(x);
    wprep_kernel<<<dim3(16, 8, 9), dim3(32, 8)>>>(w);
    conv_mma_kernel<<<dim3(32, 4, B_), 256, SMEM_BYTES>>>(bias, out);
}